// round 11
// baseline (speedup 1.0000x reference)
#include <cuda_runtime.h>
#include <cuda_bf16.h>

#define NMAX 100000
#define EMAX 1600000
#define DIM  128

__device__ int   g_deg[NMAX];
__device__ int   g_order[EMAX];
__device__ int   g_rowptr[NMAX + 1];
__device__ int   g_srcidx[EMAX];
__device__ float g_dis[NMAX];
__device__ float g_bufA[(size_t)NMAX * DIM];
__device__ float g_bufB[(size_t)NMAX * DIM];
__device__ float g_Wp[4][64 * DIM * 2];

__device__ __forceinline__ unsigned long long fma2(unsigned long long a,
                                                   unsigned long long b,
                                                   unsigned long long c) {
    unsigned long long d;
    asm("fma.rn.f32x2 %0, %1, %2, %3;" : "=l"(d) : "l"(a), "l"(b), "l"(c));
    return d;
}
__device__ __forceinline__ float hsum2(unsigned long long v) {
    float lo, hi;
    asm("mov.b64 {%0, %1}, %2;" : "=f"(lo), "=f"(hi) : "l"(v));
    return lo + hi;
}

// zero degree array + pack all 4 weight matrices (even/odd k interleave)
__global__ void k_pre(const float* __restrict__ W1, const float* __restrict__ W2,
                      const float* __restrict__ W3, const float* __restrict__ Wm,
                      int n)
{
    int i = blockIdx.x * blockDim.x + threadIdx.x;
    if (i < n) g_deg[i] = 0;
    if (i < 4 * 64 * DIM) {
        int m = i >> 13;        // matrix id, 8192 pair-slots each
        int r = i & 8191;
        const float* W = (m == 0) ? W1 : (m == 1) ? W2 : (m == 2) ? W3 : Wm;
        int p = r >> 7, c = r & 127;
        float* Wp = g_Wp[m];
        Wp[r * 2]     = W[(2 * p) * DIM + c];
        Wp[r * 2 + 1] = W[(2 * p + 1) * DIM + c];
    }
}

// histogram + remember each edge's order within its dst bucket
__global__ void k_hist(const int* __restrict__ dst, int E) {
    int i = blockIdx.x * blockDim.x + threadIdx.x;
    if (i < E) g_order[i] = atomicAdd(&g_deg[dst[i]], 1);
}

// single-block exclusive scan, 4 elements/thread; also dis = rsqrt(deg+1)
__global__ void k_scan(int n, int E) {
    __shared__ int wsum[32];
    __shared__ int carry_s;
    int tid = threadIdx.x;
    int lane = tid & 31, warp = tid >> 5;
    if (tid == 0) carry_s = 0;
    __syncthreads();
    for (int base = 0; base < n; base += 4096) {
        int i0 = base + tid * 4;
        int d0 = (i0     < n) ? g_deg[i0]     : 0;
        int d1 = (i0 + 1 < n) ? g_deg[i0 + 1] : 0;
        int d2 = (i0 + 2 < n) ? g_deg[i0 + 2] : 0;
        int d3 = (i0 + 3 < n) ? g_deg[i0 + 3] : 0;
        int tot = d0 + d1 + d2 + d3;
        int x = tot;
        #pragma unroll
        for (int o = 1; o < 32; o <<= 1) {
            int y = __shfl_up_sync(0xffffffffu, x, o);
            if (lane >= o) x += y;
        }
        if (lane == 31) wsum[warp] = x;
        __syncthreads();
        if (tid < 32) {
            int s = wsum[tid];
            #pragma unroll
            for (int o = 1; o < 32; o <<= 1) {
                int y = __shfl_up_sync(0xffffffffu, s, o);
                if (tid >= o) s += y;
            }
            wsum[tid] = s;
        }
        __syncthreads();
        int pre = carry_s + (x - tot) + ((warp > 0) ? wsum[warp - 1] : 0);
        if (i0     < n) { g_rowptr[i0]     = pre;                 g_dis[i0]     = rsqrtf((float)(d0 + 1)); }
        if (i0 + 1 < n) { g_rowptr[i0 + 1] = pre + d0;            g_dis[i0 + 1] = rsqrtf((float)(d1 + 1)); }
        if (i0 + 2 < n) { g_rowptr[i0 + 2] = pre + d0 + d1;       g_dis[i0 + 2] = rsqrtf((float)(d2 + 1)); }
        if (i0 + 3 < n) { g_rowptr[i0 + 3] = pre + d0 + d1 + d2;  g_dis[i0 + 3] = rsqrtf((float)(d3 + 1)); }
        int blocktot = wsum[31];
        __syncthreads();
        if (tid == 0) carry_s += blocktot;
        __syncthreads();
    }
    if (tid == 0) g_rowptr[n] = E;
}

// atomic-free CSR fill using precomputed order
__global__ void k_fill(const int* __restrict__ src, const int* __restrict__ dst, int E) {
    int i = blockIdx.x * blockDim.x + threadIdx.x;
    if (i < E)
        g_srcidx[g_rowptr[dst[i]] + g_order[i]] = src[i];
}

// mode 0: C = (A@W) * g_dis[row] ; mode 1: C = elu(A@W + bias)
// W staged through shared memory (two 32KB stages) -> FMA-pipe bound.
__global__ __launch_bounds__(256) void k_gemm(
    const float* __restrict__ A, const float* __restrict__ Wp,
    const float* __restrict__ bias,
    float* __restrict__ C, int n, int mode)
{
    __shared__ float Ws[8192];   // 32 p-rows x 256 floats = 32KB
    int tx = threadIdx.x & 31;
    int ty = threadIdx.x >> 5;
    int row0 = blockIdx.x * 64 + ty * 8;

    int ridx[8];
    #pragma unroll
    for (int r = 0; r < 8; r++) {
        int rr = row0 + r;
        ridx[r] = (rr < n) ? rr : (n - 1);
    }

    unsigned long long acc[8][4];
    #pragma unroll
    for (int r = 0; r < 8; r++)
        #pragma unroll
        for (int c = 0; c < 4; c++) acc[r][c] = 0ull;

    for (int kk = 0; kk < 2; kk++) {
        // stage 32KB of packed W
        {
            const float4* s = (const float4*)(Wp + kk * 8192);
            float4* d = (float4*)Ws;
            #pragma unroll
            for (int i = 0; i < 8; i++)
                d[threadIdx.x + i * 256] = __ldg(&s[threadIdx.x + i * 256]);
        }
        __syncthreads();

        #pragma unroll 4
        for (int k0 = 0; k0 < 64; k0 += 4) {
            ulonglong2 a[8];
            #pragma unroll
            for (int r = 0; r < 8; r++)
                a[r] = __ldg((const ulonglong2*)(A + (size_t)ridx[r] * DIM + kk * 64 + k0));

            #pragma unroll
            for (int half = 0; half < 2; half++) {
                int p = (k0 >> 1) + half;   // local p-row within stage
                const ulonglong2* wp = (const ulonglong2*)(Ws + p * 256 + tx * 8);
                ulonglong2 w01 = wp[0];
                ulonglong2 w23 = wp[1];
                #pragma unroll
                for (int r = 0; r < 8; r++) {
                    unsigned long long av = half ? a[r].y : a[r].x;
                    acc[r][0] = fma2(av, w01.x, acc[r][0]);
                    acc[r][1] = fma2(av, w01.y, acc[r][1]);
                    acc[r][2] = fma2(av, w23.x, acc[r][2]);
                    acc[r][3] = fma2(av, w23.y, acc[r][3]);
                }
            }
        }
        __syncthreads();
    }

    #pragma unroll
    for (int r = 0; r < 8; r++) {
        int row = row0 + r;
        if (row >= n) break;
        float4 o;
        o.x = hsum2(acc[r][0]);
        o.y = hsum2(acc[r][1]);
        o.z = hsum2(acc[r][2]);
        o.w = hsum2(acc[r][3]);
        if (mode == 0) {
            float s = __ldg(&g_dis[row]);
            o.x *= s; o.y *= s; o.z *= s; o.w *= s;
        } else {
            float4 b = __ldg(((const float4*)bias) + tx);
            o.x += b.x; o.y += b.y; o.z += b.z; o.w += b.w;
            o.x = (o.x > 0.f) ? o.x : expm1f(o.x);
            o.y = (o.y > 0.f) ? o.y : expm1f(o.y);
            o.z = (o.z > 0.f) ? o.z : expm1f(o.z);
            o.w = (o.w > 0.f) ? o.w : expm1f(o.w);
        }
        ((float4*)C)[(size_t)row * 32 + tx] = o;
    }
}

// out = relu(dis[v]*(sum_{s->v} g[s] + g[v]) + b)   (measured-best simple loop)
__global__ __launch_bounds__(256) void k_agg(
    const float* __restrict__ g, const float* __restrict__ bias,
    float* __restrict__ out, int n)
{
    int lane = threadIdx.x & 31;
    int w = threadIdx.x >> 5;
    int v = blockIdx.x * 8 + w;
    if (v >= n) return;

    const float4* g4 = (const float4*)g;
    float4 acc = __ldg(&g4[(size_t)v * 32 + lane]);   // self-loop term

    int beg = __ldg(&g_rowptr[v]);
    int end = __ldg(&g_rowptr[v + 1]);
    for (int e0 = beg; e0 < end; e0 += 32) {
        int cnt = end - e0;
        if (cnt > 32) cnt = 32;
        int s = (lane < cnt) ? __ldg(&g_srcidx[e0 + lane]) : 0;
        for (int j = 0; j < cnt; j++) {
            int sj = __shfl_sync(0xffffffffu, s, j);
            float4 gv = __ldg(&g4[(size_t)sj * 32 + lane]);
            acc.x += gv.x; acc.y += gv.y; acc.z += gv.z; acc.w += gv.w;
        }
    }

    float ds = __ldg(&g_dis[v]);
    float4 b = __ldg(((const float4*)bias) + lane);
    float4 o;
    o.x = fmaxf(fmaf(acc.x, ds, b.x), 0.f);
    o.y = fmaxf(fmaf(acc.y, ds, b.y), 0.f);
    o.z = fmaxf(fmaf(acc.z, ds, b.z), 0.f);
    o.w = fmaxf(fmaf(acc.w, ds, b.w), 0.f);
    ((float4*)out)[(size_t)v * 32 + lane] = o;
}

__global__ __launch_bounds__(256) void k_mlp2(
    const float* __restrict__ M, const float* __restrict__ W,
    const float* __restrict__ b, float* __restrict__ logits,
    float* __restrict__ probs, int n)
{
    __shared__ float Ws[DIM * 40];
    for (int i = threadIdx.x; i < DIM * 40; i += 256) Ws[i] = W[i];
    __syncthreads();

    int rl = threadIdx.x >> 3;
    int jg = threadIdx.x & 7;
    int row = blockIdx.x * 32 + rl;
    int rowc = (row < n) ? row : (n - 1);

    float acc[5] = {0.f, 0.f, 0.f, 0.f, 0.f};
    const float* mrow = M + (size_t)rowc * DIM;
    for (int k = 0; k < DIM; k += 4) {
        float4 a = __ldg((const float4*)(mrow + k));
        #pragma unroll
        for (int t = 0; t < 5; t++) {
            int j = jg * 5 + t;
            acc[t] += a.x * Ws[(k    ) * 40 + j];
            acc[t] += a.y * Ws[(k + 1) * 40 + j];
            acc[t] += a.z * Ws[(k + 2) * 40 + j];
            acc[t] += a.w * Ws[(k + 3) * 40 + j];
        }
    }
    #pragma unroll
    for (int t = 0; t < 5; t++) acc[t] += __ldg(&b[jg * 5 + t]);

    float mx = acc[0];
    #pragma unroll
    for (int t = 1; t < 5; t++) mx = fmaxf(mx, acc[t]);
    #pragma unroll
    for (int o = 1; o < 8; o <<= 1)
        mx = fmaxf(mx, __shfl_xor_sync(0xffffffffu, mx, o));
    float e[5], s = 0.f;
    #pragma unroll
    for (int t = 0; t < 5; t++) { e[t] = expf(acc[t] - mx); s += e[t]; }
    #pragma unroll
    for (int o = 1; o < 8; o <<= 1)
        s += __shfl_xor_sync(0xffffffffu, s, o);
    float inv = 1.f / s;

    if (row < n) {
        #pragma unroll
        for (int t = 0; t < 5; t++) {
            int j = jg * 5 + t;
            logits[(size_t)row * 40 + j] = acc[t];
            probs[(size_t)row * 40 + j]  = e[t] * inv;
        }
    }
}

extern "C" void kernel_launch(void* const* d_in, const int* in_sizes, int n_in,
                              void* d_out, int out_size)
{
    const float* x   = (const float*)d_in[0];
    const int*   ei  = (const int*)d_in[1];
    const float* W1  = (const float*)d_in[2];
    const float* b1  = (const float*)d_in[3];
    const float* W2  = (const float*)d_in[4];
    const float* b2  = (const float*)d_in[5];
    const float* W3  = (const float*)d_in[6];
    const float* b3  = (const float*)d_in[7];
    const float* Wm1 = (const float*)d_in[8];
    const float* bm1 = (const float*)d_in[9];
    const float* Wm2 = (const float*)d_in[10];
    const float* bm2 = (const float*)d_in[11];

    int n = in_sizes[0] / DIM;
    int E = in_sizes[1] / 2;
    const int* src = ei;
    const int* dst = ei + E;

    float* out    = (float*)d_out;
    float* logits = out;
    float* probs  = out + (size_t)n * 40;
    float* emb    = out + (size_t)n * 80;

    float *bufA, *bufB, *Wp;
    cudaGetSymbolAddress((void**)&bufA, g_bufA);
    cudaGetSymbolAddress((void**)&bufB, g_bufB);
    cudaGetSymbolAddress((void**)&Wp,   g_Wp);
    float* Wp1 = Wp;
    float* Wp2 = Wp + 64 * DIM * 2;
    float* Wp3 = Wp + 2 * 64 * DIM * 2;
    float* Wpm = Wp + 3 * 64 * DIM * 2;

    k_pre <<<(n + 255) / 256, 256>>>(W1, W2, W3, Wm1, n);
    k_hist<<<(E + 255) / 256, 256>>>(dst, E);
    k_scan<<<1, 1024>>>(n, E);
    k_fill<<<(E + 255) / 256, 256>>>(src, dst, E);

    int gg = (n + 63) / 64;
    int ag = (n + 7) / 8;

    k_gemm<<<gg, 256>>>(x,    Wp1, nullptr, bufA, n, 0);
    k_agg <<<ag, 256>>>(bufA, b1, bufB, n);
    k_gemm<<<gg, 256>>>(bufB, Wp2, nullptr, bufA, n, 0);
    k_agg <<<ag, 256>>>(bufA, b2, bufB, n);
    k_gemm<<<gg, 256>>>(bufB, Wp3, nullptr, bufA, n, 0);
    k_agg <<<ag, 256>>>(bufA, b3, emb, n);

    k_gemm<<<gg, 256>>>(emb,  Wpm, bm1, bufA, n, 1);
    k_mlp2<<<(n + 31) / 32, 256>>>(bufA, Wm2, bm2, logits, probs, n);
}

// round 12
// speedup vs baseline: 1.0242x; 1.0242x over previous
#include <cuda_runtime.h>
#include <cuda_bf16.h>

#define NMAX 100000
#define EMAX 1600000
#define DIM  128

__device__ int   g_deg[NMAX];
__device__ int   g_order[EMAX];
__device__ int   g_rowptr[NMAX + 1];
__device__ int   g_srcidx[EMAX];
__device__ float g_dis[NMAX];
__device__ float g_bufA[(size_t)NMAX * DIM];
__device__ float g_bufB[(size_t)NMAX * DIM];
__device__ float g_Wp[4][64 * DIM * 2];

__device__ __forceinline__ unsigned long long fma2(unsigned long long a,
                                                   unsigned long long b,
                                                   unsigned long long c) {
    unsigned long long d;
    asm("fma.rn.f32x2 %0, %1, %2, %3;" : "=l"(d) : "l"(a), "l"(b), "l"(c));
    return d;
}
__device__ __forceinline__ float hsum2(unsigned long long v) {
    float lo, hi;
    asm("mov.b64 {%0, %1}, %2;" : "=f"(lo), "=f"(hi) : "l"(v));
    return lo + hi;
}

// zero degree array + pack all 4 weight matrices.
// Layout per k-pair row p (256 floats = 1KB):
//   seg0 (floats [0,128)):   lane t owns cols 4t,4t+1   -> [t*4 + (c&1)*2 + parity]
//   seg1 (floats [128,256)): lane t owns cols 4t+2,4t+3 -> [128 + t*4 + (c&1)*2 + parity]
// => both LDS.128 in the GEMM have contiguous 16B lane stride (conflict-free).
__global__ void k_pre(const float* __restrict__ W1, const float* __restrict__ W2,
                      const float* __restrict__ W3, const float* __restrict__ Wm,
                      int n)
{
    int i = blockIdx.x * blockDim.x + threadIdx.x;
    if (i < n) g_deg[i] = 0;
    if (i < 4 * 64 * DIM) {
        int m = i >> 13;        // matrix id, 8192 (p,c) slots each
        int r = i & 8191;
        const float* W = (m == 0) ? W1 : (m == 1) ? W2 : (m == 2) ? W3 : Wm;
        int p = r >> 7, c = r & 127;
        int base = p * 256 + (((c & 3) >= 2) ? 128 : 0) + (c >> 2) * 4 + (c & 1) * 2;
        float* Wp = g_Wp[m];
        Wp[base]     = W[(2 * p) * DIM + c];
        Wp[base + 1] = W[(2 * p + 1) * DIM + c];
    }
}

// histogram + remember each edge's order within its dst bucket
__global__ void k_hist(const int* __restrict__ dst, int E) {
    int i = blockIdx.x * blockDim.x + threadIdx.x;
    if (i < E) g_order[i] = atomicAdd(&g_deg[dst[i]], 1);
}

// single-block exclusive scan, 4 elements/thread; also dis = rsqrt(deg+1)
__global__ void k_scan(int n, int E) {
    __shared__ int wsum[32];
    __shared__ int carry_s;
    int tid = threadIdx.x;
    int lane = tid & 31, warp = tid >> 5;
    if (tid == 0) carry_s = 0;
    __syncthreads();
    for (int base = 0; base < n; base += 4096) {
        int i0 = base + tid * 4;
        int d0 = (i0     < n) ? g_deg[i0]     : 0;
        int d1 = (i0 + 1 < n) ? g_deg[i0 + 1] : 0;
        int d2 = (i0 + 2 < n) ? g_deg[i0 + 2] : 0;
        int d3 = (i0 + 3 < n) ? g_deg[i0 + 3] : 0;
        int tot = d0 + d1 + d2 + d3;
        int x = tot;
        #pragma unroll
        for (int o = 1; o < 32; o <<= 1) {
            int y = __shfl_up_sync(0xffffffffu, x, o);
            if (lane >= o) x += y;
        }
        if (lane == 31) wsum[warp] = x;
        __syncthreads();
        if (tid < 32) {
            int s = wsum[tid];
            #pragma unroll
            for (int o = 1; o < 32; o <<= 1) {
                int y = __shfl_up_sync(0xffffffffu, s, o);
                if (tid >= o) s += y;
            }
            wsum[tid] = s;
        }
        __syncthreads();
        int pre = carry_s + (x - tot) + ((warp > 0) ? wsum[warp - 1] : 0);
        if (i0     < n) { g_rowptr[i0]     = pre;                 g_dis[i0]     = rsqrtf((float)(d0 + 1)); }
        if (i0 + 1 < n) { g_rowptr[i0 + 1] = pre + d0;            g_dis[i0 + 1] = rsqrtf((float)(d1 + 1)); }
        if (i0 + 2 < n) { g_rowptr[i0 + 2] = pre + d0 + d1;       g_dis[i0 + 2] = rsqrtf((float)(d2 + 1)); }
        if (i0 + 3 < n) { g_rowptr[i0 + 3] = pre + d0 + d1 + d2;  g_dis[i0 + 3] = rsqrtf((float)(d3 + 1)); }
        int blocktot = wsum[31];
        __syncthreads();
        if (tid == 0) carry_s += blocktot;
        __syncthreads();
    }
    if (tid == 0) g_rowptr[n] = E;
}

// atomic-free CSR fill using precomputed order
__global__ void k_fill(const int* __restrict__ src, const int* __restrict__ dst, int E) {
    int i = blockIdx.x * blockDim.x + threadIdx.x;
    if (i < E)
        g_srcidx[g_rowptr[dst[i]] + g_order[i]] = src[i];
}

// mode 0: C = (A@W) * g_dis[row] ; mode 1: C = elu(A@W + bias)
// W staged through shared memory, conflict-free LDS.128 (16B lane stride).
__global__ __launch_bounds__(256) void k_gemm(
    const float* __restrict__ A, const float* __restrict__ Wp,
    const float* __restrict__ bias,
    float* __restrict__ C, int n, int mode)
{
    __shared__ float Ws[8192];   // 32 p-rows x 256 floats = 32KB per stage
    int tx = threadIdx.x & 31;
    int ty = threadIdx.x >> 5;
    int row0 = blockIdx.x * 64 + ty * 8;

    int ridx[8];
    #pragma unroll
    for (int r = 0; r < 8; r++) {
        int rr = row0 + r;
        ridx[r] = (rr < n) ? rr : (n - 1);
    }

    unsigned long long acc[8][4];
    #pragma unroll
    for (int r = 0; r < 8; r++)
        #pragma unroll
        for (int c = 0; c < 4; c++) acc[r][c] = 0ull;

    for (int kk = 0; kk < 2; kk++) {
        {
            const float4* s = (const float4*)(Wp + kk * 8192);
            float4* d = (float4*)Ws;
            #pragma unroll
            for (int i = 0; i < 8; i++)
                d[threadIdx.x + i * 256] = __ldg(&s[threadIdx.x + i * 256]);
        }
        __syncthreads();

        #pragma unroll 4
        for (int k0 = 0; k0 < 64; k0 += 4) {
            ulonglong2 a[8];
            #pragma unroll
            for (int r = 0; r < 8; r++)
                a[r] = __ldg((const ulonglong2*)(A + (size_t)ridx[r] * DIM + kk * 64 + k0));

            #pragma unroll
            for (int half = 0; half < 2; half++) {
                int p = (k0 >> 1) + half;   // local p-row within stage
                ulonglong2 w01 = *(const ulonglong2*)(Ws + p * 256 + tx * 4);
                ulonglong2 w23 = *(const ulonglong2*)(Ws + p * 256 + 128 + tx * 4);
                #pragma unroll
                for (int r = 0; r < 8; r++) {
                    unsigned long long av = half ? a[r].y : a[r].x;
                    acc[r][0] = fma2(av, w01.x, acc[r][0]);
                    acc[r][1] = fma2(av, w01.y, acc[r][1]);
                    acc[r][2] = fma2(av, w23.x, acc[r][2]);
                    acc[r][3] = fma2(av, w23.y, acc[r][3]);
                }
            }
        }
        __syncthreads();
    }

    #pragma unroll
    for (int r = 0; r < 8; r++) {
        int row = row0 + r;
        if (row >= n) break;
        float4 o;
        o.x = hsum2(acc[r][0]);
        o.y = hsum2(acc[r][1]);
        o.z = hsum2(acc[r][2]);
        o.w = hsum2(acc[r][3]);
        if (mode == 0) {
            float s = __ldg(&g_dis[row]);
            o.x *= s; o.y *= s; o.z *= s; o.w *= s;
        } else {
            float4 b = __ldg(((const float4*)bias) + tx);
            o.x += b.x; o.y += b.y; o.z += b.z; o.w += b.w;
            o.x = (o.x > 0.f) ? o.x : expm1f(o.x);
            o.y = (o.y > 0.f) ? o.y : expm1f(o.y);
            o.z = (o.z > 0.f) ? o.z : expm1f(o.z);
            o.w = (o.w > 0.f) ? o.w : expm1f(o.w);
        }
        ((float4*)C)[(size_t)row * 32 + tx] = o;
    }
}

// out = relu(dis[v]*(sum_{s->v} g[s] + g[v]) + b)
__global__ __launch_bounds__(256) void k_agg(
    const float* __restrict__ g, const float* __restrict__ bias,
    float* __restrict__ out, int n)
{
    int lane = threadIdx.x & 31;
    int w = threadIdx.x >> 5;
    int v = blockIdx.x * 8 + w;
    if (v >= n) return;

    const float4* g4 = (const float4*)g;
    float4 acc = __ldg(&g4[(size_t)v * 32 + lane]);   // self-loop term

    int beg = __ldg(&g_rowptr[v]);
    int end = __ldg(&g_rowptr[v + 1]);
    for (int e0 = beg; e0 < end; e0 += 32) {
        int cnt = end - e0;
        if (cnt > 32) cnt = 32;
        int s = (lane < cnt) ? __ldg(&g_srcidx[e0 + lane]) : 0;
        for (int j = 0; j < cnt; j++) {
            int sj = __shfl_sync(0xffffffffu, s, j);
            float4 gv = __ldg(&g4[(size_t)sj * 32 + lane]);
            acc.x += gv.x; acc.y += gv.y; acc.z += gv.z; acc.w += gv.w;
        }
    }

    float ds = __ldg(&g_dis[v]);
    float4 b = __ldg(((const float4*)bias) + lane);
    float4 o;
    o.x = fmaxf(fmaf(acc.x, ds, b.x), 0.f);
    o.y = fmaxf(fmaf(acc.y, ds, b.y), 0.f);
    o.z = fmaxf(fmaf(acc.z, ds, b.z), 0.f);
    o.w = fmaxf(fmaf(acc.w, ds, b.w), 0.f);
    ((float4*)out)[(size_t)v * 32 + lane] = o;
}

__global__ __launch_bounds__(256) void k_mlp2(
    const float* __restrict__ M, const float* __restrict__ W,
    const float* __restrict__ b, float* __restrict__ logits,
    float* __restrict__ probs, int n)
{
    __shared__ float Ws[DIM * 40];
    for (int i = threadIdx.x; i < DIM * 40; i += 256) Ws[i] = W[i];
    __syncthreads();

    int rl = threadIdx.x >> 3;
    int jg = threadIdx.x & 7;
    int row = blockIdx.x * 32 + rl;
    int rowc = (row < n) ? row : (n - 1);

    float acc[5] = {0.f, 0.f, 0.f, 0.f, 0.f};
    const float* mrow = M + (size_t)rowc * DIM;
    for (int k = 0; k < DIM; k += 4) {
        float4 a = __ldg((const float4*)(mrow + k));
        #pragma unroll
        for (int t = 0; t < 5; t++) {
            int j = jg * 5 + t;
            acc[t] += a.x * Ws[(k    ) * 40 + j];
            acc[t] += a.y * Ws[(k + 1) * 40 + j];
            acc[t] += a.z * Ws[(k + 2) * 40 + j];
            acc[t] += a.w * Ws[(k + 3) * 40 + j];
        }
    }
    #pragma unroll
    for (int t = 0; t < 5; t++) acc[t] += __ldg(&b[jg * 5 + t]);

    float mx = acc[0];
    #pragma unroll
    for (int t = 1; t < 5; t++) mx = fmaxf(mx, acc[t]);
    #pragma unroll
    for (int o = 1; o < 8; o <<= 1)
        mx = fmaxf(mx, __shfl_xor_sync(0xffffffffu, mx, o));
    float e[5], s = 0.f;
    #pragma unroll
    for (int t = 0; t < 5; t++) { e[t] = expf(acc[t] - mx); s += e[t]; }
    #pragma unroll
    for (int o = 1; o < 8; o <<= 1)
        s += __shfl_xor_sync(0xffffffffu, s, o);
    float inv = 1.f / s;

    if (row < n) {
        #pragma unroll
        for (int t = 0; t < 5; t++) {
            int j = jg * 5 + t;
            logits[(size_t)row * 40 + j] = acc[t];
            probs[(size_t)row * 40 + j]  = e[t] * inv;
        }
    }
}

extern "C" void kernel_launch(void* const* d_in, const int* in_sizes, int n_in,
                              void* d_out, int out_size)
{
    const float* x   = (const float*)d_in[0];
    const int*   ei  = (const int*)d_in[1];
    const float* W1  = (const float*)d_in[2];
    const float* b1  = (const float*)d_in[3];
    const float* W2  = (const float*)d_in[4];
    const float* b2  = (const float*)d_in[5];
    const float* W3  = (const float*)d_in[6];
    const float* b3  = (const float*)d_in[7];
    const float* Wm1 = (const float*)d_in[8];
    const float* bm1 = (const float*)d_in[9];
    const float* Wm2 = (const float*)d_in[10];
    const float* bm2 = (const float*)d_in[11];

    int n = in_sizes[0] / DIM;
    int E = in_sizes[1] / 2;
    const int* src = ei;
    const int* dst = ei + E;

    float* out    = (float*)d_out;
    float* logits = out;
    float* probs  = out + (size_t)n * 40;
    float* emb    = out + (size_t)n * 80;

    float *bufA, *bufB, *Wp;
    cudaGetSymbolAddress((void**)&bufA, g_bufA);
    cudaGetSymbolAddress((void**)&bufB, g_bufB);
    cudaGetSymbolAddress((void**)&Wp,   g_Wp);
    float* Wp1 = Wp;
    float* Wp2 = Wp + 64 * DIM * 2;
    float* Wp3 = Wp + 2 * 64 * DIM * 2;
    float* Wpm = Wp + 3 * 64 * DIM * 2;

    int gg = (n + 63) / 64;
    int ag = (n + 7) / 8;

    k_pre <<<(n + 255) / 256, 256>>>(W1, W2, W3, Wm1, n);
    k_hist<<<(E + 255) / 256, 256>>>(dst, E);
    k_scan<<<1, 1024>>>(n, E);
    // gemm1 placed before k_fill (no dependence) so the profiled launch slot
    // (consistently app-launch #3) captures k_gemm next round.
    k_gemm<<<gg, 256>>>(x, Wp1, nullptr, bufA, n, 0);
    k_fill<<<(E + 255) / 256, 256>>>(src, dst, E);

    k_agg <<<ag, 256>>>(bufA, b1, bufB, n);
    k_gemm<<<gg, 256>>>(bufB, Wp2, nullptr, bufA, n, 0);
    k_agg <<<ag, 256>>>(bufA, b2, bufB, n);
    k_gemm<<<gg, 256>>>(bufB, Wp3, nullptr, bufA, n, 0);
    k_agg <<<ag, 256>>>(bufA, b3, emb, n);

    k_gemm<<<gg, 256>>>(emb,  Wpm, bm1, bufA, n, 1);
    k_mlp2<<<(n + 31) / 32, 256>>>(bufA, Wm2, bm2, logits, probs, n);
}

// round 13
// speedup vs baseline: 1.0243x; 1.0001x over previous
#include <cuda_runtime.h>
#include <cuda_bf16.h>

#define NMAX 100000
#define EMAX 1600000
#define DIM  128

__device__ int   g_deg[NMAX];
__device__ int   g_order[EMAX];
__device__ int   g_rowptr[NMAX + 1];
__device__ int   g_srcidx[EMAX];
__device__ float g_dis[NMAX];
__device__ float g_bufA[(size_t)NMAX * DIM];
__device__ float g_bufB[(size_t)NMAX * DIM];
__device__ float g_Wp[4][64 * DIM * 2];

__device__ __forceinline__ unsigned long long fma2(unsigned long long a,
                                                   unsigned long long b,
                                                   unsigned long long c) {
    unsigned long long d;
    asm("fma.rn.f32x2 %0, %1, %2, %3;" : "=l"(d) : "l"(a), "l"(b), "l"(c));
    return d;
}
__device__ __forceinline__ float hsum2(unsigned long long v) {
    float lo, hi;
    asm("mov.b64 {%0, %1}, %2;" : "=f"(lo), "=f"(hi) : "l"(v));
    return lo + hi;
}

// zero degree array + pack all 4 weight matrices.
// Layout per k-pair row p (256 floats = 1KB):
//   seg0 (floats [0,128)):   lane t owns cols 4t,4t+1   -> [t*4 + (c&1)*2 + parity]
//   seg1 (floats [128,256)): lane t owns cols 4t+2,4t+3 -> [128 + t*4 + (c&1)*2 + parity]
// => both LDS.128 in the GEMM have contiguous 16B lane stride (conflict-free).
__global__ void k_pre(const float* __restrict__ W1, const float* __restrict__ W2,
                      const float* __restrict__ W3, const float* __restrict__ Wm,
                      int n)
{
    int i = blockIdx.x * blockDim.x + threadIdx.x;
    if (i < n) g_deg[i] = 0;
    if (i < 4 * 64 * DIM) {
        int m = i >> 13;        // matrix id, 8192 (p,c) slots each
        int r = i & 8191;
        const float* W = (m == 0) ? W1 : (m == 1) ? W2 : (m == 2) ? W3 : Wm;
        int p = r >> 7, c = r & 127;
        int base = p * 256 + (((c & 3) >= 2) ? 128 : 0) + (c >> 2) * 4 + (c & 1) * 2;
        float* Wp = g_Wp[m];
        Wp[base]     = W[(2 * p) * DIM + c];
        Wp[base + 1] = W[(2 * p + 1) * DIM + c];
    }
}

// histogram + remember each edge's order within its dst bucket
__global__ void k_hist(const int* __restrict__ dst, int E) {
    int i = blockIdx.x * blockDim.x + threadIdx.x;
    if (i < E) g_order[i] = atomicAdd(&g_deg[dst[i]], 1);
}

// single-block exclusive scan, 4 elements/thread; also dis = rsqrt(deg+1)
__global__ void k_scan(int n, int E) {
    __shared__ int wsum[32];
    __shared__ int carry_s;
    int tid = threadIdx.x;
    int lane = tid & 31, warp = tid >> 5;
    if (tid == 0) carry_s = 0;
    __syncthreads();
    for (int base = 0; base < n; base += 4096) {
        int i0 = base + tid * 4;
        int d0 = (i0     < n) ? g_deg[i0]     : 0;
        int d1 = (i0 + 1 < n) ? g_deg[i0 + 1] : 0;
        int d2 = (i0 + 2 < n) ? g_deg[i0 + 2] : 0;
        int d3 = (i0 + 3 < n) ? g_deg[i0 + 3] : 0;
        int tot = d0 + d1 + d2 + d3;
        int x = tot;
        #pragma unroll
        for (int o = 1; o < 32; o <<= 1) {
            int y = __shfl_up_sync(0xffffffffu, x, o);
            if (lane >= o) x += y;
        }
        if (lane == 31) wsum[warp] = x;
        __syncthreads();
        if (tid < 32) {
            int s = wsum[tid];
            #pragma unroll
            for (int o = 1; o < 32; o <<= 1) {
                int y = __shfl_up_sync(0xffffffffu, s, o);
                if (tid >= o) s += y;
            }
            wsum[tid] = s;
        }
        __syncthreads();
        int pre = carry_s + (x - tot) + ((warp > 0) ? wsum[warp - 1] : 0);
        if (i0     < n) { g_rowptr[i0]     = pre;                 g_dis[i0]     = rsqrtf((float)(d0 + 1)); }
        if (i0 + 1 < n) { g_rowptr[i0 + 1] = pre + d0;            g_dis[i0 + 1] = rsqrtf((float)(d1 + 1)); }
        if (i0 + 2 < n) { g_rowptr[i0 + 2] = pre + d0 + d1;       g_dis[i0 + 2] = rsqrtf((float)(d2 + 1)); }
        if (i0 + 3 < n) { g_rowptr[i0 + 3] = pre + d0 + d1 + d2;  g_dis[i0 + 3] = rsqrtf((float)(d3 + 1)); }
        int blocktot = wsum[31];
        __syncthreads();
        if (tid == 0) carry_s += blocktot;
        __syncthreads();
    }
    if (tid == 0) g_rowptr[n] = E;
}

// atomic-free CSR fill using precomputed order
__global__ void k_fill(const int* __restrict__ src, const int* __restrict__ dst, int E) {
    int i = blockIdx.x * blockDim.x + threadIdx.x;
    if (i < E)
        g_srcidx[g_rowptr[dst[i]] + g_order[i]] = src[i];
}

// mode 0: C = (A@W) * g_dis[row] ; mode 1: C = elu(A@W + bias)
// W staged through shared memory, conflict-free LDS.128 (16B lane stride).
__global__ __launch_bounds__(256) void k_gemm(
    const float* __restrict__ A, const float* __restrict__ Wp,
    const float* __restrict__ bias,
    float* __restrict__ C, int n, int mode)
{
    __shared__ float Ws[8192];   // 32 p-rows x 256 floats = 32KB per stage
    int tx = threadIdx.x & 31;
    int ty = threadIdx.x >> 5;
    int row0 = blockIdx.x * 64 + ty * 8;

    int ridx[8];
    #pragma unroll
    for (int r = 0; r < 8; r++) {
        int rr = row0 + r;
        ridx[r] = (rr < n) ? rr : (n - 1);
    }

    unsigned long long acc[8][4];
    #pragma unroll
    for (int r = 0; r < 8; r++)
        #pragma unroll
        for (int c = 0; c < 4; c++) acc[r][c] = 0ull;

    for (int kk = 0; kk < 2; kk++) {
        {
            const float4* s = (const float4*)(Wp + kk * 8192);
            float4* d = (float4*)Ws;
            #pragma unroll
            for (int i = 0; i < 8; i++)
                d[threadIdx.x + i * 256] = __ldg(&s[threadIdx.x + i * 256]);
        }
        __syncthreads();

        #pragma unroll 4
        for (int k0 = 0; k0 < 64; k0 += 4) {
            ulonglong2 a[8];
            #pragma unroll
            for (int r = 0; r < 8; r++)
                a[r] = __ldg((const ulonglong2*)(A + (size_t)ridx[r] * DIM + kk * 64 + k0));

            #pragma unroll
            for (int half = 0; half < 2; half++) {
                int p = (k0 >> 1) + half;   // local p-row within stage
                ulonglong2 w01 = *(const ulonglong2*)(Ws + p * 256 + tx * 4);
                ulonglong2 w23 = *(const ulonglong2*)(Ws + p * 256 + 128 + tx * 4);
                #pragma unroll
                for (int r = 0; r < 8; r++) {
                    unsigned long long av = half ? a[r].y : a[r].x;
                    acc[r][0] = fma2(av, w01.x, acc[r][0]);
                    acc[r][1] = fma2(av, w01.y, acc[r][1]);
                    acc[r][2] = fma2(av, w23.x, acc[r][2]);
                    acc[r][3] = fma2(av, w23.y, acc[r][3]);
                }
            }
        }
        __syncthreads();
    }

    #pragma unroll
    for (int r = 0; r < 8; r++) {
        int row = row0 + r;
        if (row >= n) break;
        float4 o;
        o.x = hsum2(acc[r][0]);
        o.y = hsum2(acc[r][1]);
        o.z = hsum2(acc[r][2]);
        o.w = hsum2(acc[r][3]);
        if (mode == 0) {
            float s = __ldg(&g_dis[row]);
            o.x *= s; o.y *= s; o.z *= s; o.w *= s;
        } else {
            float4 b = __ldg(((const float4*)bias) + tx);
            o.x += b.x; o.y += b.y; o.z += b.z; o.w += b.w;
            o.x = (o.x > 0.f) ? o.x : expm1f(o.x);
            o.y = (o.y > 0.f) ? o.y : expm1f(o.y);
            o.z = (o.z > 0.f) ? o.z : expm1f(o.z);
            o.w = (o.w > 0.f) ? o.w : expm1f(o.w);
        }
        ((float4*)C)[(size_t)row * 32 + tx] = o;
    }
}

// out = relu(dis[v]*(sum_{s->v} g[s] + g[v]) + b)
__global__ __launch_bounds__(256) void k_agg(
    const float* __restrict__ g, const float* __restrict__ bias,
    float* __restrict__ out, int n)
{
    int lane = threadIdx.x & 31;
    int w = threadIdx.x >> 5;
    int v = blockIdx.x * 8 + w;
    if (v >= n) return;

    const float4* g4 = (const float4*)g;
    float4 acc = __ldg(&g4[(size_t)v * 32 + lane]);   // self-loop term

    int beg = __ldg(&g_rowptr[v]);
    int end = __ldg(&g_rowptr[v + 1]);
    for (int e0 = beg; e0 < end; e0 += 32) {
        int cnt = end - e0;
        if (cnt > 32) cnt = 32;
        int s = (lane < cnt) ? __ldg(&g_srcidx[e0 + lane]) : 0;
        for (int j = 0; j < cnt; j++) {
            int sj = __shfl_sync(0xffffffffu, s, j);
            float4 gv = __ldg(&g4[(size_t)sj * 32 + lane]);
            acc.x += gv.x; acc.y += gv.y; acc.z += gv.z; acc.w += gv.w;
        }
    }

    float ds = __ldg(&g_dis[v]);
    float4 b = __ldg(((const float4*)bias) + lane);
    float4 o;
    o.x = fmaxf(fmaf(acc.x, ds, b.x), 0.f);
    o.y = fmaxf(fmaf(acc.y, ds, b.y), 0.f);
    o.z = fmaxf(fmaf(acc.z, ds, b.z), 0.f);
    o.w = fmaxf(fmaf(acc.w, ds, b.w), 0.f);
    ((float4*)out)[(size_t)v * 32 + lane] = o;
}

__global__ __launch_bounds__(256) void k_mlp2(
    const float* __restrict__ M, const float* __restrict__ W,
    const float* __restrict__ b, float* __restrict__ logits,
    float* __restrict__ probs, int n)
{
    __shared__ float Ws[DIM * 40];
    for (int i = threadIdx.x; i < DIM * 40; i += 256) Ws[i] = W[i];
    __syncthreads();

    int rl = threadIdx.x >> 3;
    int jg = threadIdx.x & 7;
    int row = blockIdx.x * 32 + rl;
    int rowc = (row < n) ? row : (n - 1);

    float acc[5] = {0.f, 0.f, 0.f, 0.f, 0.f};
    const float* mrow = M + (size_t)rowc * DIM;
    for (int k = 0; k < DIM; k += 4) {
        float4 a = __ldg((const float4*)(mrow + k));
        #pragma unroll
        for (int t = 0; t < 5; t++) {
            int j = jg * 5 + t;
            acc[t] += a.x * Ws[(k    ) * 40 + j];
            acc[t] += a.y * Ws[(k + 1) * 40 + j];
            acc[t] += a.z * Ws[(k + 2) * 40 + j];
            acc[t] += a.w * Ws[(k + 3) * 40 + j];
        }
    }
    #pragma unroll
    for (int t = 0; t < 5; t++) acc[t] += __ldg(&b[jg * 5 + t]);

    float mx = acc[0];
    #pragma unroll
    for (int t = 1; t < 5; t++) mx = fmaxf(mx, acc[t]);
    #pragma unroll
    for (int o = 1; o < 8; o <<= 1)
        mx = fmaxf(mx, __shfl_xor_sync(0xffffffffu, mx, o));
    float e[5], s = 0.f;
    #pragma unroll
    for (int t = 0; t < 5; t++) { e[t] = expf(acc[t] - mx); s += e[t]; }
    #pragma unroll
    for (int o = 1; o < 8; o <<= 1)
        s += __shfl_xor_sync(0xffffffffu, s, o);
    float inv = 1.f / s;

    if (row < n) {
        #pragma unroll
        for (int t = 0; t < 5; t++) {
            int j = jg * 5 + t;
            logits[(size_t)row * 40 + j] = acc[t];
            probs[(size_t)row * 40 + j]  = e[t] * inv;
        }
    }
}

extern "C" void kernel_launch(void* const* d_in, const int* in_sizes, int n_in,
                              void* d_out, int out_size)
{
    const float* x   = (const float*)d_in[0];
    const int*   ei  = (const int*)d_in[1];
    const float* W1  = (const float*)d_in[2];
    const float* b1  = (const float*)d_in[3];
    const float* W2  = (const float*)d_in[4];
    const float* b2  = (const float*)d_in[5];
    const float* W3  = (const float*)d_in[6];
    const float* b3  = (const float*)d_in[7];
    const float* Wm1 = (const float*)d_in[8];
    const float* bm1 = (const float*)d_in[9];
    const float* Wm2 = (const float*)d_in[10];
    const float* bm2 = (const float*)d_in[11];

    int n = in_sizes[0] / DIM;
    int E = in_sizes[1] / 2;
    const int* src = ei;
    const int* dst = ei + E;

    float* out    = (float*)d_out;
    float* logits = out;
    float* probs  = out + (size_t)n * 40;
    float* emb    = out + (size_t)n * 80;

    float *bufA, *bufB, *Wp;
    cudaGetSymbolAddress((void**)&bufA, g_bufA);
    cudaGetSymbolAddress((void**)&bufB, g_bufB);
    cudaGetSymbolAddress((void**)&Wp,   g_Wp);
    float* Wp1 = Wp;
    float* Wp2 = Wp + 64 * DIM * 2;
    float* Wp3 = Wp + 2 * 64 * DIM * 2;
    float* Wpm = Wp + 3 * 64 * DIM * 2;

    int gg = (n + 63) / 64;
    int ag = (n + 7) / 8;

    k_pre <<<(n + 255) / 256, 256>>>(W1, W2, W3, Wm1, n);
    k_hist<<<(E + 255) / 256, 256>>>(dst, E);
    k_scan<<<1, 1024>>>(n, E);
    // gemm1 placed before k_fill (no dependence) so the profiled launch slot
    // (consistently app-launch #3) captures k_gemm next round.
    k_gemm<<<gg, 256>>>(x, Wp1, nullptr, bufA, n, 0);
    k_fill<<<(E + 255) / 256, 256>>>(src, dst, E);

    k_agg <<<ag, 256>>>(bufA, b1, bufB, n);
    k_gemm<<<gg, 256>>>(bufB, Wp2, nullptr, bufA, n, 0);
    k_agg <<<ag, 256>>>(bufA, b2, bufB, n);
    k_gemm<<<gg, 256>>>(bufB, Wp3, nullptr, bufA, n, 0);
    k_agg <<<ag, 256>>>(bufA, b3, emb, n);

    k_gemm<<<gg, 256>>>(emb,  Wpm, bm1, bufA, n, 1);
    k_mlp2<<<(n + 31) / 32, 256>>>(bufA, Wm2, bm2, logits, probs, n);
}

// round 14
// speedup vs baseline: 1.0252x; 1.0009x over previous
#include <cuda_runtime.h>
#include <cuda_bf16.h>

#define NMAX 100000
#define EMAX 1600000
#define DIM  128

__device__ int   g_deg[NMAX];
__device__ int   g_order[EMAX];
__device__ int   g_rowptr[NMAX + 1];
__device__ int   g_srcidx[EMAX];
__device__ float g_dis[NMAX];
__device__ float g_bufA[(size_t)NMAX * DIM];
__device__ float g_bufB[(size_t)NMAX * DIM];
__device__ float g_Wp[4][64 * DIM * 2];

__device__ __forceinline__ unsigned long long fma2(unsigned long long a,
                                                   unsigned long long b,
                                                   unsigned long long c) {
    unsigned long long d;
    asm("fma.rn.f32x2 %0, %1, %2, %3;" : "=l"(d) : "l"(a), "l"(b), "l"(c));
    return d;
}
__device__ __forceinline__ float hsum2(unsigned long long v) {
    float lo, hi;
    asm("mov.b64 {%0, %1}, %2;" : "=f"(lo), "=f"(hi) : "l"(v));
    return lo + hi;
}

// zero degree array + pack all 4 weight matrices.
// Layout per k-pair row p (256 floats = 1KB):
//   seg0 (floats [0,128)):   lane t owns cols 4t,4t+1   -> [t*4 + (c&1)*2 + parity]
//   seg1 (floats [128,256)): lane t owns cols 4t+2,4t+3 -> [128 + t*4 + (c&1)*2 + parity]
// => both LDS.128 in the GEMM have contiguous 16B lane stride (conflict-free).
__global__ void k_pre(const float* __restrict__ W1, const float* __restrict__ W2,
                      const float* __restrict__ W3, const float* __restrict__ Wm,
                      int n)
{
    int i = blockIdx.x * blockDim.x + threadIdx.x;
    if (i < n) g_deg[i] = 0;
    if (i < 4 * 64 * DIM) {
        int m = i >> 13;        // matrix id, 8192 (p,c) slots each
        int r = i & 8191;
        const float* W = (m == 0) ? W1 : (m == 1) ? W2 : (m == 2) ? W3 : Wm;
        int p = r >> 7, c = r & 127;
        int base = p * 256 + (((c & 3) >= 2) ? 128 : 0) + (c >> 2) * 4 + (c & 1) * 2;
        float* Wp = g_Wp[m];
        Wp[base]     = W[(2 * p) * DIM + c];
        Wp[base + 1] = W[(2 * p + 1) * DIM + c];
    }
}

// histogram + remember each edge's order within its dst bucket
__global__ void k_hist(const int* __restrict__ dst, int E) {
    int i = blockIdx.x * blockDim.x + threadIdx.x;
    if (i < E) g_order[i] = atomicAdd(&g_deg[dst[i]], 1);
}

// single-block exclusive scan, 4 elements/thread; also dis = rsqrt(deg+1)
__global__ void k_scan(int n, int E) {
    __shared__ int wsum[32];
    __shared__ int carry_s;
    int tid = threadIdx.x;
    int lane = tid & 31, warp = tid >> 5;
    if (tid == 0) carry_s = 0;
    __syncthreads();
    for (int base = 0; base < n; base += 4096) {
        int i0 = base + tid * 4;
        int d0 = (i0     < n) ? g_deg[i0]     : 0;
        int d1 = (i0 + 1 < n) ? g_deg[i0 + 1] : 0;
        int d2 = (i0 + 2 < n) ? g_deg[i0 + 2] : 0;
        int d3 = (i0 + 3 < n) ? g_deg[i0 + 3] : 0;
        int tot = d0 + d1 + d2 + d3;
        int x = tot;
        #pragma unroll
        for (int o = 1; o < 32; o <<= 1) {
            int y = __shfl_up_sync(0xffffffffu, x, o);
            if (lane >= o) x += y;
        }
        if (lane == 31) wsum[warp] = x;
        __syncthreads();
        if (tid < 32) {
            int s = wsum[tid];
            #pragma unroll
            for (int o = 1; o < 32; o <<= 1) {
                int y = __shfl_up_sync(0xffffffffu, s, o);
                if (tid >= o) s += y;
            }
            wsum[tid] = s;
        }
        __syncthreads();
        int pre = carry_s + (x - tot) + ((warp > 0) ? wsum[warp - 1] : 0);
        if (i0     < n) { g_rowptr[i0]     = pre;                 g_dis[i0]     = rsqrtf((float)(d0 + 1)); }
        if (i0 + 1 < n) { g_rowptr[i0 + 1] = pre + d0;            g_dis[i0 + 1] = rsqrtf((float)(d1 + 1)); }
        if (i0 + 2 < n) { g_rowptr[i0 + 2] = pre + d0 + d1;       g_dis[i0 + 2] = rsqrtf((float)(d2 + 1)); }
        if (i0 + 3 < n) { g_rowptr[i0 + 3] = pre + d0 + d1 + d2;  g_dis[i0 + 3] = rsqrtf((float)(d3 + 1)); }
        int blocktot = wsum[31];
        __syncthreads();
        if (tid == 0) carry_s += blocktot;
        __syncthreads();
    }
    if (tid == 0) g_rowptr[n] = E;
}

// atomic-free CSR fill using precomputed order
__global__ void k_fill(const int* __restrict__ src, const int* __restrict__ dst, int E) {
    int i = blockIdx.x * blockDim.x + threadIdx.x;
    if (i < E)
        g_srcidx[g_rowptr[dst[i]] + g_order[i]] = src[i];
}

// mode 0: C = (A@W) * g_dis[row] ; mode 1: C = elu(A@W + bias)
// W staged through shared memory, conflict-free LDS.128 (16B lane stride).
__global__ __launch_bounds__(256) void k_gemm(
    const float* __restrict__ A, const float* __restrict__ Wp,
    const float* __restrict__ bias,
    float* __restrict__ C, int n, int mode)
{
    __shared__ float Ws[8192];   // 32 p-rows x 256 floats = 32KB per stage
    int tx = threadIdx.x & 31;
    int ty = threadIdx.x >> 5;
    int row0 = blockIdx.x * 64 + ty * 8;

    int ridx[8];
    #pragma unroll
    for (int r = 0; r < 8; r++) {
        int rr = row0 + r;
        ridx[r] = (rr < n) ? rr : (n - 1);
    }

    unsigned long long acc[8][4];
    #pragma unroll
    for (int r = 0; r < 8; r++)
        #pragma unroll
        for (int c = 0; c < 4; c++) acc[r][c] = 0ull;

    for (int kk = 0; kk < 2; kk++) {
        {
            const float4* s = (const float4*)(Wp + kk * 8192);
            float4* d = (float4*)Ws;
            #pragma unroll
            for (int i = 0; i < 8; i++)
                d[threadIdx.x + i * 256] = __ldg(&s[threadIdx.x + i * 256]);
        }
        __syncthreads();

        #pragma unroll 4
        for (int k0 = 0; k0 < 64; k0 += 4) {
            ulonglong2 a[8];
            #pragma unroll
            for (int r = 0; r < 8; r++)
                a[r] = __ldg((const ulonglong2*)(A + (size_t)ridx[r] * DIM + kk * 64 + k0));

            #pragma unroll
            for (int half = 0; half < 2; half++) {
                int p = (k0 >> 1) + half;   // local p-row within stage
                ulonglong2 w01 = *(const ulonglong2*)(Ws + p * 256 + tx * 4);
                ulonglong2 w23 = *(const ulonglong2*)(Ws + p * 256 + 128 + tx * 4);
                #pragma unroll
                for (int r = 0; r < 8; r++) {
                    unsigned long long av = half ? a[r].y : a[r].x;
                    acc[r][0] = fma2(av, w01.x, acc[r][0]);
                    acc[r][1] = fma2(av, w01.y, acc[r][1]);
                    acc[r][2] = fma2(av, w23.x, acc[r][2]);
                    acc[r][3] = fma2(av, w23.y, acc[r][3]);
                }
            }
        }
        __syncthreads();
    }

    #pragma unroll
    for (int r = 0; r < 8; r++) {
        int row = row0 + r;
        if (row >= n) break;
        float4 o;
        o.x = hsum2(acc[r][0]);
        o.y = hsum2(acc[r][1]);
        o.z = hsum2(acc[r][2]);
        o.w = hsum2(acc[r][3]);
        if (mode == 0) {
            float s = __ldg(&g_dis[row]);
            o.x *= s; o.y *= s; o.z *= s; o.w *= s;
        } else {
            float4 b = __ldg(((const float4*)bias) + tx);
            o.x += b.x; o.y += b.y; o.z += b.z; o.w += b.w;
            o.x = (o.x > 0.f) ? o.x : expm1f(o.x);
            o.y = (o.y > 0.f) ? o.y : expm1f(o.y);
            o.z = (o.z > 0.f) ? o.z : expm1f(o.z);
            o.w = (o.w > 0.f) ? o.w : expm1f(o.w);
        }
        ((float4*)C)[(size_t)row * 32 + tx] = o;
    }
}

// out = relu(dis[v]*(sum_{s->v} g[s] + g[v]) + b)
__global__ __launch_bounds__(256) void k_agg(
    const float* __restrict__ g, const float* __restrict__ bias,
    float* __restrict__ out, int n)
{
    int lane = threadIdx.x & 31;
    int w = threadIdx.x >> 5;
    int v = blockIdx.x * 8 + w;
    if (v >= n) return;

    const float4* g4 = (const float4*)g;
    float4 acc = __ldg(&g4[(size_t)v * 32 + lane]);   // self-loop term

    int beg = __ldg(&g_rowptr[v]);
    int end = __ldg(&g_rowptr[v + 1]);
    for (int e0 = beg; e0 < end; e0 += 32) {
        int cnt = end - e0;
        if (cnt > 32) cnt = 32;
        int s = (lane < cnt) ? __ldg(&g_srcidx[e0 + lane]) : 0;
        for (int j = 0; j < cnt; j++) {
            int sj = __shfl_sync(0xffffffffu, s, j);
            float4 gv = __ldg(&g4[(size_t)sj * 32 + lane]);
            acc.x += gv.x; acc.y += gv.y; acc.z += gv.z; acc.w += gv.w;
        }
    }

    float ds = __ldg(&g_dis[v]);
    float4 b = __ldg(((const float4*)bias) + lane);
    float4 o;
    o.x = fmaxf(fmaf(acc.x, ds, b.x), 0.f);
    o.y = fmaxf(fmaf(acc.y, ds, b.y), 0.f);
    o.z = fmaxf(fmaf(acc.z, ds, b.z), 0.f);
    o.w = fmaxf(fmaf(acc.w, ds, b.w), 0.f);
    ((float4*)out)[(size_t)v * 32 + lane] = o;
}

__global__ __launch_bounds__(256) void k_mlp2(
    const float* __restrict__ M, const float* __restrict__ W,
    const float* __restrict__ b, float* __restrict__ logits,
    float* __restrict__ probs, int n)
{
    __shared__ float Ws[DIM * 40];
    for (int i = threadIdx.x; i < DIM * 40; i += 256) Ws[i] = W[i];
    __syncthreads();

    int rl = threadIdx.x >> 3;
    int jg = threadIdx.x & 7;
    int row = blockIdx.x * 32 + rl;
    int rowc = (row < n) ? row : (n - 1);

    float acc[5] = {0.f, 0.f, 0.f, 0.f, 0.f};
    const float* mrow = M + (size_t)rowc * DIM;
    for (int k = 0; k < DIM; k += 4) {
        float4 a = __ldg((const float4*)(mrow + k));
        #pragma unroll
        for (int t = 0; t < 5; t++) {
            int j = jg * 5 + t;
            acc[t] += a.x * Ws[(k    ) * 40 + j];
            acc[t] += a.y * Ws[(k + 1) * 40 + j];
            acc[t] += a.z * Ws[(k + 2) * 40 + j];
            acc[t] += a.w * Ws[(k + 3) * 40 + j];
        }
    }
    #pragma unroll
    for (int t = 0; t < 5; t++) acc[t] += __ldg(&b[jg * 5 + t]);

    float mx = acc[0];
    #pragma unroll
    for (int t = 1; t < 5; t++) mx = fmaxf(mx, acc[t]);
    #pragma unroll
    for (int o = 1; o < 8; o <<= 1)
        mx = fmaxf(mx, __shfl_xor_sync(0xffffffffu, mx, o));
    float e[5], s = 0.f;
    #pragma unroll
    for (int t = 0; t < 5; t++) { e[t] = expf(acc[t] - mx); s += e[t]; }
    #pragma unroll
    for (int o = 1; o < 8; o <<= 1)
        s += __shfl_xor_sync(0xffffffffu, s, o);
    float inv = 1.f / s;

    if (row < n) {
        #pragma unroll
        for (int t = 0; t < 5; t++) {
            int j = jg * 5 + t;
            logits[(size_t)row * 40 + j] = acc[t];
            probs[(size_t)row * 40 + j]  = e[t] * inv;
        }
    }
}

extern "C" void kernel_launch(void* const* d_in, const int* in_sizes, int n_in,
                              void* d_out, int out_size)
{
    const float* x   = (const float*)d_in[0];
    const int*   ei  = (const int*)d_in[1];
    const float* W1  = (const float*)d_in[2];
    const float* b1  = (const float*)d_in[3];
    const float* W2  = (const float*)d_in[4];
    const float* b2  = (const float*)d_in[5];
    const float* W3  = (const float*)d_in[6];
    const float* b3  = (const float*)d_in[7];
    const float* Wm1 = (const float*)d_in[8];
    const float* bm1 = (const float*)d_in[9];
    const float* Wm2 = (const float*)d_in[10];
    const float* bm2 = (const float*)d_in[11];

    int n = in_sizes[0] / DIM;
    int E = in_sizes[1] / 2;
    const int* src = ei;
    const int* dst = ei + E;

    float* out    = (float*)d_out;
    float* logits = out;
    float* probs  = out + (size_t)n * 40;
    float* emb    = out + (size_t)n * 80;

    float *bufA, *bufB, *Wp;
    cudaGetSymbolAddress((void**)&bufA, g_bufA);
    cudaGetSymbolAddress((void**)&bufB, g_bufB);
    cudaGetSymbolAddress((void**)&Wp,   g_Wp);
    float* Wp1 = Wp;
    float* Wp2 = Wp + 64 * DIM * 2;
    float* Wp3 = Wp + 2 * 64 * DIM * 2;
    float* Wpm = Wp + 3 * 64 * DIM * 2;

    int gg = (n + 63) / 64;
    int ag = (n + 7) / 8;

    k_pre <<<(n + 255) / 256, 256>>>(W1, W2, W3, Wm1, n);
    k_hist<<<(E + 255) / 256, 256>>>(dst, E);
    k_scan<<<1, 1024>>>(n, E);
    // gemm1 placed before k_fill (no dependence) so the profiled launch slot
    // (consistently app-launch #3) captures k_gemm next round.
    k_gemm<<<gg, 256>>>(x, Wp1, nullptr, bufA, n, 0);
    k_fill<<<(E + 255) / 256, 256>>>(src, dst, E);

    k_agg <<<ag, 256>>>(bufA, b1, bufB, n);
    k_gemm<<<gg, 256>>>(bufB, Wp2, nullptr, bufA, n, 0);
    k_agg <<<ag, 256>>>(bufA, b2, bufB, n);
    k_gemm<<<gg, 256>>>(bufB, Wp3, nullptr, bufA, n, 0);
    k_agg <<<ag, 256>>>(bufA, b3, emb, n);

    k_gemm<<<gg, 256>>>(emb,  Wpm, bm1, bufA, n, 1);
    k_mlp2<<<(n + 31) / 32, 256>>>(bufA, Wm2, bm2, logits, probs, n);
}

// round 15
// speedup vs baseline: 1.3712x; 1.3375x over previous
#include <cuda_runtime.h>
#include <cuda_bf16.h>

#define NMAX 100000
#define EMAX 1600000
#define DIM  128

__device__ int   g_deg[NMAX];
__device__ int   g_order[EMAX];
__device__ int   g_rowptr[NMAX + 1];
__device__ int   g_srcidx[EMAX];
__device__ float g_dis[NMAX];
__device__ float g_bufA[(size_t)NMAX * DIM];
__device__ float g_bufB[(size_t)NMAX * DIM];
__device__ float g_Wp[4][64 * DIM * 2];

__device__ __forceinline__ unsigned long long fma2(unsigned long long a,
                                                   unsigned long long b,
                                                   unsigned long long c) {
    unsigned long long d;
    asm("fma.rn.f32x2 %0, %1, %2, %3;" : "=l"(d) : "l"(a), "l"(b), "l"(c));
    return d;
}
__device__ __forceinline__ float hsum2(unsigned long long v) {
    float lo, hi;
    asm("mov.b64 {%0, %1}, %2;" : "=f"(lo), "=f"(hi) : "l"(v));
    return lo + hi;
}

// zero degree array + pack all 4 weight matrices.
// Layout per k-pair row p (256 floats = 1KB):
//   seg0 (floats [0,128)):   lane t owns cols 4t,4t+1   -> [t*4 + (c&1)*2 + parity]
//   seg1 (floats [128,256)): lane t owns cols 4t+2,4t+3 -> [128 + t*4 + (c&1)*2 + parity]
// => both LDS.128 in the GEMM have contiguous 16B lane stride (conflict-free).
__global__ void k_pre(const float* __restrict__ W1, const float* __restrict__ W2,
                      const float* __restrict__ W3, const float* __restrict__ Wm,
                      int n)
{
    int i = blockIdx.x * blockDim.x + threadIdx.x;
    if (i < n) g_deg[i] = 0;
    if (i < 4 * 64 * DIM) {
        int m = i >> 13;        // matrix id, 8192 (p,c) slots each
        int r = i & 8191;
        const float* W = (m == 0) ? W1 : (m == 1) ? W2 : (m == 2) ? W3 : Wm;
        int p = r >> 7, c = r & 127;
        int base = p * 256 + (((c & 3) >= 2) ? 128 : 0) + (c >> 2) * 4 + (c & 1) * 2;
        float* Wp = g_Wp[m];
        Wp[base]     = W[(2 * p) * DIM + c];
        Wp[base + 1] = W[(2 * p + 1) * DIM + c];
    }
}

// histogram + remember each edge's order within its dst bucket
__global__ void k_hist(const int* __restrict__ dst, int E) {
    int i = blockIdx.x * blockDim.x + threadIdx.x;
    if (i < E) g_order[i] = atomicAdd(&g_deg[dst[i]], 1);
}

// single-block exclusive scan, 4 elements/thread; also dis = rsqrt(deg+1)
__global__ void k_scan(int n, int E) {
    __shared__ int wsum[32];
    __shared__ int carry_s;
    int tid = threadIdx.x;
    int lane = tid & 31, warp = tid >> 5;
    if (tid == 0) carry_s = 0;
    __syncthreads();
    for (int base = 0; base < n; base += 4096) {
        int i0 = base + tid * 4;
        int d0 = (i0     < n) ? g_deg[i0]     : 0;
        int d1 = (i0 + 1 < n) ? g_deg[i0 + 1] : 0;
        int d2 = (i0 + 2 < n) ? g_deg[i0 + 2] : 0;
        int d3 = (i0 + 3 < n) ? g_deg[i0 + 3] : 0;
        int tot = d0 + d1 + d2 + d3;
        int x = tot;
        #pragma unroll
        for (int o = 1; o < 32; o <<= 1) {
            int y = __shfl_up_sync(0xffffffffu, x, o);
            if (lane >= o) x += y;
        }
        if (lane == 31) wsum[warp] = x;
        __syncthreads();
        if (tid < 32) {
            int s = wsum[tid];
            #pragma unroll
            for (int o = 1; o < 32; o <<= 1) {
                int y = __shfl_up_sync(0xffffffffu, s, o);
                if (tid >= o) s += y;
            }
            wsum[tid] = s;
        }
        __syncthreads();
        int pre = carry_s + (x - tot) + ((warp > 0) ? wsum[warp - 1] : 0);
        if (i0     < n) { g_rowptr[i0]     = pre;                 g_dis[i0]     = rsqrtf((float)(d0 + 1)); }
        if (i0 + 1 < n) { g_rowptr[i0 + 1] = pre + d0;            g_dis[i0 + 1] = rsqrtf((float)(d1 + 1)); }
        if (i0 + 2 < n) { g_rowptr[i0 + 2] = pre + d0 + d1;       g_dis[i0 + 2] = rsqrtf((float)(d2 + 1)); }
        if (i0 + 3 < n) { g_rowptr[i0 + 3] = pre + d0 + d1 + d2;  g_dis[i0 + 3] = rsqrtf((float)(d3 + 1)); }
        int blocktot = wsum[31];
        __syncthreads();
        if (tid == 0) carry_s += blocktot;
        __syncthreads();
    }
    if (tid == 0) g_rowptr[n] = E;
}

// atomic-free CSR fill using precomputed order
__global__ void k_fill(const int* __restrict__ src, const int* __restrict__ dst, int E) {
    int i = blockIdx.x * blockDim.x + threadIdx.x;
    if (i < E)
        g_srcidx[g_rowptr[dst[i]] + g_order[i]] = src[i];
}

// mode 0: C = (A@W) * g_dis[row] ; mode 1: C = elu(A@W + bias)
// 32 rows/block, 4 rows/thread -> ~75 regs -> 3 CTAs/SM (occ 37.5%).
__global__ __launch_bounds__(256, 3) void k_gemm(
    const float* __restrict__ A, const float* __restrict__ Wp,
    const float* __restrict__ bias,
    float* __restrict__ C, int n, int mode)
{
    __shared__ float Ws[8192];   // 32 p-rows x 256 floats = 32KB per stage
    int tx = threadIdx.x & 31;
    int ty = threadIdx.x >> 5;
    int row0 = blockIdx.x * 32 + ty * 4;

    int ridx[4];
    #pragma unroll
    for (int r = 0; r < 4; r++) {
        int rr = row0 + r;
        ridx[r] = (rr < n) ? rr : (n - 1);
    }

    unsigned long long acc[4][4];
    #pragma unroll
    for (int r = 0; r < 4; r++)
        #pragma unroll
        for (int c = 0; c < 4; c++) acc[r][c] = 0ull;

    for (int kk = 0; kk < 2; kk++) {
        {
            const float4* s = (const float4*)(Wp + kk * 8192);
            float4* d = (float4*)Ws;
            #pragma unroll
            for (int i = 0; i < 8; i++)
                d[threadIdx.x + i * 256] = __ldg(&s[threadIdx.x + i * 256]);
        }
        __syncthreads();

        #pragma unroll 4
        for (int k0 = 0; k0 < 64; k0 += 4) {
            ulonglong2 a[4];
            #pragma unroll
            for (int r = 0; r < 4; r++)
                a[r] = __ldg((const ulonglong2*)(A + (size_t)ridx[r] * DIM + kk * 64 + k0));

            #pragma unroll
            for (int half = 0; half < 2; half++) {
                int p = (k0 >> 1) + half;   // local p-row within stage
                ulonglong2 w01 = *(const ulonglong2*)(Ws + p * 256 + tx * 4);
                ulonglong2 w23 = *(const ulonglong2*)(Ws + p * 256 + 128 + tx * 4);
                #pragma unroll
                for (int r = 0; r < 4; r++) {
                    unsigned long long av = half ? a[r].y : a[r].x;
                    acc[r][0] = fma2(av, w01.x, acc[r][0]);
                    acc[r][1] = fma2(av, w01.y, acc[r][1]);
                    acc[r][2] = fma2(av, w23.x, acc[r][2]);
                    acc[r][3] = fma2(av, w23.y, acc[r][3]);
                }
            }
        }
        __syncthreads();
    }

    #pragma unroll
    for (int r = 0; r < 4; r++) {
        int row = row0 + r;
        if (row >= n) break;
        float4 o;
        o.x = hsum2(acc[r][0]);
        o.y = hsum2(acc[r][1]);
        o.z = hsum2(acc[r][2]);
        o.w = hsum2(acc[r][3]);
        if (mode == 0) {
            float s = __ldg(&g_dis[row]);
            o.x *= s; o.y *= s; o.z *= s; o.w *= s;
        } else {
            float4 b = __ldg(((const float4*)bias) + tx);
            o.x += b.x; o.y += b.y; o.z += b.z; o.w += b.w;
            o.x = (o.x > 0.f) ? o.x : expm1f(o.x);
            o.y = (o.y > 0.f) ? o.y : expm1f(o.y);
            o.z = (o.z > 0.f) ? o.z : expm1f(o.z);
            o.w = (o.w > 0.f) ? o.w : expm1f(o.w);
        }
        ((float4*)C)[(size_t)row * 32 + tx] = o;
    }
}

// out = relu(dis[v]*(sum_{s->v} g[s] + g[v]) + b)
__global__ __launch_bounds__(256) void k_agg(
    const float* __restrict__ g, const float* __restrict__ bias,
    float* __restrict__ out, int n)
{
    int lane = threadIdx.x & 31;
    int w = threadIdx.x >> 5;
    int v = blockIdx.x * 8 + w;
    if (v >= n) return;

    const float4* g4 = (const float4*)g;
    float4 acc = __ldg(&g4[(size_t)v * 32 + lane]);   // self-loop term

    int beg = __ldg(&g_rowptr[v]);
    int end = __ldg(&g_rowptr[v + 1]);
    for (int e0 = beg; e0 < end; e0 += 32) {
        int cnt = end - e0;
        if (cnt > 32) cnt = 32;
        int s = (lane < cnt) ? __ldg(&g_srcidx[e0 + lane]) : 0;
        for (int j = 0; j < cnt; j++) {
            int sj = __shfl_sync(0xffffffffu, s, j);
            float4 gv = __ldg(&g4[(size_t)sj * 32 + lane]);
            acc.x += gv.x; acc.y += gv.y; acc.z += gv.z; acc.w += gv.w;
        }
    }

    float ds = __ldg(&g_dis[v]);
    float4 b = __ldg(((const float4*)bias) + lane);
    float4 o;
    o.x = fmaxf(fmaf(acc.x, ds, b.x), 0.f);
    o.y = fmaxf(fmaf(acc.y, ds, b.y), 0.f);
    o.z = fmaxf(fmaf(acc.z, ds, b.z), 0.f);
    o.w = fmaxf(fmaf(acc.w, ds, b.w), 0.f);
    ((float4*)out)[(size_t)v * 32 + lane] = o;
}

__global__ __launch_bounds__(256) void k_mlp2(
    const float* __restrict__ M, const float* __restrict__ W,
    const float* __restrict__ b, float* __restrict__ logits,
    float* __restrict__ probs, int n)
{
    __shared__ float Ws[DIM * 40];
    for (int i = threadIdx.x; i < DIM * 40; i += 256) Ws[i] = W[i];
    __syncthreads();

    int rl = threadIdx.x >> 3;
    int jg = threadIdx.x & 7;
    int row = blockIdx.x * 32 + rl;
    int rowc = (row < n) ? row : (n - 1);

    float acc[5] = {0.f, 0.f, 0.f, 0.f, 0.f};
    const float* mrow = M + (size_t)rowc * DIM;
    for (int k = 0; k < DIM; k += 4) {
        float4 a = __ldg((const float4*)(mrow + k));
        #pragma unroll
        for (int t = 0; t < 5; t++) {
            int j = jg * 5 + t;
            acc[t] += a.x * Ws[(k    ) * 40 + j];
            acc[t] += a.y * Ws[(k + 1) * 40 + j];
            acc[t] += a.z * Ws[(k + 2) * 40 + j];
            acc[t] += a.w * Ws[(k + 3) * 40 + j];
        }
    }
    #pragma unroll
    for (int t = 0; t < 5; t++) acc[t] += __ldg(&b[jg * 5 + t]);

    float mx = acc[0];
    #pragma unroll
    for (int t = 1; t < 5; t++) mx = fmaxf(mx, acc[t]);
    #pragma unroll
    for (int o = 1; o < 8; o <<= 1)
        mx = fmaxf(mx, __shfl_xor_sync(0xffffffffu, mx, o));
    float e[5], s = 0.f;
    #pragma unroll
    for (int t = 0; t < 5; t++) { e[t] = expf(acc[t] - mx); s += e[t]; }
    #pragma unroll
    for (int o = 1; o < 8; o <<= 1)
        s += __shfl_xor_sync(0xffffffffu, s, o);
    float inv = 1.f / s;

    if (row < n) {
        #pragma unroll
        for (int t = 0; t < 5; t++) {
            int j = jg * 5 + t;
            logits[(size_t)row * 40 + j] = acc[t];
            probs[(size_t)row * 40 + j]  = e[t] * inv;
        }
    }
}

extern "C" void kernel_launch(void* const* d_in, const int* in_sizes, int n_in,
                              void* d_out, int out_size)
{
    const float* x   = (const float*)d_in[0];
    const int*   ei  = (const int*)d_in[1];
    const float* W1  = (const float*)d_in[2];
    const float* b1  = (const float*)d_in[3];
    const float* W2  = (const float*)d_in[4];
    const float* b2  = (const float*)d_in[5];
    const float* W3  = (const float*)d_in[6];
    const float* b3  = (const float*)d_in[7];
    const float* Wm1 = (const float*)d_in[8];
    const float* bm1 = (const float*)d_in[9];
    const float* Wm2 = (const float*)d_in[10];
    const float* bm2 = (const float*)d_in[11];

    int n = in_sizes[0] / DIM;
    int E = in_sizes[1] / 2;
    const int* src = ei;
    const int* dst = ei + E;

    float* out    = (float*)d_out;
    float* logits = out;
    float* probs  = out + (size_t)n * 40;
    float* emb    = out + (size_t)n * 80;

    float *bufA, *bufB, *Wp;
    cudaGetSymbolAddress((void**)&bufA, g_bufA);
    cudaGetSymbolAddress((void**)&bufB, g_bufB);
    cudaGetSymbolAddress((void**)&Wp,   g_Wp);
    float* Wp1 = Wp;
    float* Wp2 = Wp + 64 * DIM * 2;
    float* Wp3 = Wp + 2 * 64 * DIM * 2;
    float* Wpm = Wp + 3 * 64 * DIM * 2;

    int gg = (n + 31) / 32;
    int ag = (n + 7) / 8;

    k_pre <<<(n + 255) / 256, 256>>>(W1, W2, W3, Wm1, n);
    k_hist<<<(E + 255) / 256, 256>>>(dst, E);
    k_scan<<<1, 1024>>>(n, E);
    // gemm1 kept in the profiled launch slot
    k_gemm<<<gg, 256>>>(x, Wp1, nullptr, bufA, n, 0);
    k_fill<<<(E + 255) / 256, 256>>>(src, dst, E);

    k_agg <<<ag, 256>>>(bufA, b1, bufB, n);
    k_gemm<<<gg, 256>>>(bufB, Wp2, nullptr, bufA, n, 0);
    k_agg <<<ag, 256>>>(bufA, b2, bufB, n);
    k_gemm<<<gg, 256>>>(bufB, Wp3, nullptr, bufA, n, 0);
    k_agg <<<ag, 256>>>(bufA, b3, emb, n);

    k_gemm<<<gg, 256>>>(emb,  Wpm, bm1, bufA, n, 1);
    k_mlp2<<<(n + 31) / 32, 256>>>(bufA, Wm2, bm2, logits, probs, n);
}

// round 16
// speedup vs baseline: 1.3713x; 1.0000x over previous
#include <cuda_runtime.h>
#include <cuda_bf16.h>

#define NMAX 100000
#define EMAX 1600000
#define DIM  128

__device__ int   g_deg[NMAX];
__device__ int   g_order[EMAX];
__device__ int   g_rowptr[NMAX + 1];
__device__ int   g_srcidx[EMAX];
__device__ float g_dis[NMAX];
__device__ float g_bufA[(size_t)NMAX * DIM];
__device__ float g_bufB[(size_t)NMAX * DIM];
__device__ float g_Wp[4][64 * DIM * 2];

__device__ __forceinline__ unsigned long long fma2(unsigned long long a,
                                                   unsigned long long b,
                                                   unsigned long long c) {
    unsigned long long d;
    asm("fma.rn.f32x2 %0, %1, %2, %3;" : "=l"(d) : "l"(a), "l"(b), "l"(c));
    return d;
}
__device__ __forceinline__ float hsum2(unsigned long long v) {
    float lo, hi;
    asm("mov.b64 {%0, %1}, %2;" : "=f"(lo), "=f"(hi) : "l"(v));
    return lo + hi;
}

// zero degree array + pack all 4 weight matrices.
// Layout per k-pair row p (256 floats = 1KB):
//   seg0 (floats [0,128)):   lane t owns cols 4t,4t+1   -> [t*4 + (c&1)*2 + parity]
//   seg1 (floats [128,256)): lane t owns cols 4t+2,4t+3 -> [128 + t*4 + (c&1)*2 + parity]
// => both LDS.128 in the GEMM have contiguous 16B lane stride (conflict-free).
__global__ void k_pre(const float* __restrict__ W1, const float* __restrict__ W2,
                      const float* __restrict__ W3, const float* __restrict__ Wm,
                      int n)
{
    int i = blockIdx.x * blockDim.x + threadIdx.x;
    if (i < n) g_deg[i] = 0;
    if (i < 4 * 64 * DIM) {
        int m = i >> 13;        // matrix id, 8192 (p,c) slots each
        int r = i & 8191;
        const float* W = (m == 0) ? W1 : (m == 1) ? W2 : (m == 2) ? W3 : Wm;
        int p = r >> 7, c = r & 127;
        int base = p * 256 + (((c & 3) >= 2) ? 128 : 0) + (c >> 2) * 4 + (c & 1) * 2;
        float* Wp = g_Wp[m];
        Wp[base]     = W[(2 * p) * DIM + c];
        Wp[base + 1] = W[(2 * p + 1) * DIM + c];
    }
}

// histogram + remember each edge's order within its dst bucket
__global__ void k_hist(const int* __restrict__ dst, int E) {
    int i = blockIdx.x * blockDim.x + threadIdx.x;
    if (i < E) g_order[i] = atomicAdd(&g_deg[dst[i]], 1);
}

// single-block exclusive scan, 4 elements/thread; also dis = rsqrt(deg+1)
__global__ void k_scan(int n, int E) {
    __shared__ int wsum[32];
    __shared__ int carry_s;
    int tid = threadIdx.x;
    int lane = tid & 31, warp = tid >> 5;
    if (tid == 0) carry_s = 0;
    __syncthreads();
    for (int base = 0; base < n; base += 4096) {
        int i0 = base + tid * 4;
        int d0 = (i0     < n) ? g_deg[i0]     : 0;
        int d1 = (i0 + 1 < n) ? g_deg[i0 + 1] : 0;
        int d2 = (i0 + 2 < n) ? g_deg[i0 + 2] : 0;
        int d3 = (i0 + 3 < n) ? g_deg[i0 + 3] : 0;
        int tot = d0 + d1 + d2 + d3;
        int x = tot;
        #pragma unroll
        for (int o = 1; o < 32; o <<= 1) {
            int y = __shfl_up_sync(0xffffffffu, x, o);
            if (lane >= o) x += y;
        }
        if (lane == 31) wsum[warp] = x;
        __syncthreads();
        if (tid < 32) {
            int s = wsum[tid];
            #pragma unroll
            for (int o = 1; o < 32; o <<= 1) {
                int y = __shfl_up_sync(0xffffffffu, s, o);
                if (tid >= o) s += y;
            }
            wsum[tid] = s;
        }
        __syncthreads();
        int pre = carry_s + (x - tot) + ((warp > 0) ? wsum[warp - 1] : 0);
        if (i0     < n) { g_rowptr[i0]     = pre;                 g_dis[i0]     = rsqrtf((float)(d0 + 1)); }
        if (i0 + 1 < n) { g_rowptr[i0 + 1] = pre + d0;            g_dis[i0 + 1] = rsqrtf((float)(d1 + 1)); }
        if (i0 + 2 < n) { g_rowptr[i0 + 2] = pre + d0 + d1;       g_dis[i0 + 2] = rsqrtf((float)(d2 + 1)); }
        if (i0 + 3 < n) { g_rowptr[i0 + 3] = pre + d0 + d1 + d2;  g_dis[i0 + 3] = rsqrtf((float)(d3 + 1)); }
        int blocktot = wsum[31];
        __syncthreads();
        if (tid == 0) carry_s += blocktot;
        __syncthreads();
    }
    if (tid == 0) g_rowptr[n] = E;
}

// atomic-free CSR fill using precomputed order
__global__ void k_fill(const int* __restrict__ src, const int* __restrict__ dst, int E) {
    int i = blockIdx.x * blockDim.x + threadIdx.x;
    if (i < E)
        g_srcidx[g_rowptr[dst[i]] + g_order[i]] = src[i];
}

// mode 0: C = (A@W) * g_dis[row] ; mode 1: C = elu(A@W + bias)
// 32 rows/block, 4 rows/thread -> ~75 regs -> 3 CTAs/SM (occ 37.5%).
__global__ __launch_bounds__(256, 3) void k_gemm(
    const float* __restrict__ A, const float* __restrict__ Wp,
    const float* __restrict__ bias,
    float* __restrict__ C, int n, int mode)
{
    __shared__ float Ws[8192];   // 32 p-rows x 256 floats = 32KB per stage
    int tx = threadIdx.x & 31;
    int ty = threadIdx.x >> 5;
    int row0 = blockIdx.x * 32 + ty * 4;

    int ridx[4];
    #pragma unroll
    for (int r = 0; r < 4; r++) {
        int rr = row0 + r;
        ridx[r] = (rr < n) ? rr : (n - 1);
    }

    unsigned long long acc[4][4];
    #pragma unroll
    for (int r = 0; r < 4; r++)
        #pragma unroll
        for (int c = 0; c < 4; c++) acc[r][c] = 0ull;

    for (int kk = 0; kk < 2; kk++) {
        {
            const float4* s = (const float4*)(Wp + kk * 8192);
            float4* d = (float4*)Ws;
            #pragma unroll
            for (int i = 0; i < 8; i++)
                d[threadIdx.x + i * 256] = __ldg(&s[threadIdx.x + i * 256]);
        }
        __syncthreads();

        #pragma unroll 4
        for (int k0 = 0; k0 < 64; k0 += 4) {
            ulonglong2 a[4];
            #pragma unroll
            for (int r = 0; r < 4; r++)
                a[r] = __ldg((const ulonglong2*)(A + (size_t)ridx[r] * DIM + kk * 64 + k0));

            #pragma unroll
            for (int half = 0; half < 2; half++) {
                int p = (k0 >> 1) + half;   // local p-row within stage
                ulonglong2 w01 = *(const ulonglong2*)(Ws + p * 256 + tx * 4);
                ulonglong2 w23 = *(const ulonglong2*)(Ws + p * 256 + 128 + tx * 4);
                #pragma unroll
                for (int r = 0; r < 4; r++) {
                    unsigned long long av = half ? a[r].y : a[r].x;
                    acc[r][0] = fma2(av, w01.x, acc[r][0]);
                    acc[r][1] = fma2(av, w01.y, acc[r][1]);
                    acc[r][2] = fma2(av, w23.x, acc[r][2]);
                    acc[r][3] = fma2(av, w23.y, acc[r][3]);
                }
            }
        }
        __syncthreads();
    }

    #pragma unroll
    for (int r = 0; r < 4; r++) {
        int row = row0 + r;
        if (row >= n) break;
        float4 o;
        o.x = hsum2(acc[r][0]);
        o.y = hsum2(acc[r][1]);
        o.z = hsum2(acc[r][2]);
        o.w = hsum2(acc[r][3]);
        if (mode == 0) {
            float s = __ldg(&g_dis[row]);
            o.x *= s; o.y *= s; o.z *= s; o.w *= s;
        } else {
            float4 b = __ldg(((const float4*)bias) + tx);
            o.x += b.x; o.y += b.y; o.z += b.z; o.w += b.w;
            o.x = (o.x > 0.f) ? o.x : expm1f(o.x);
            o.y = (o.y > 0.f) ? o.y : expm1f(o.y);
            o.z = (o.z > 0.f) ? o.z : expm1f(o.z);
            o.w = (o.w > 0.f) ? o.w : expm1f(o.w);
        }
        ((float4*)C)[(size_t)row * 32 + tx] = o;
    }
}

// out = relu(dis[v]*(sum_{s->v} g[s] + g[v]) + b)
__global__ __launch_bounds__(256) void k_agg(
    const float* __restrict__ g, const float* __restrict__ bias,
    float* __restrict__ out, int n)
{
    int lane = threadIdx.x & 31;
    int w = threadIdx.x >> 5;
    int v = blockIdx.x * 8 + w;
    if (v >= n) return;

    const float4* g4 = (const float4*)g;
    float4 acc = __ldg(&g4[(size_t)v * 32 + lane]);   // self-loop term

    int beg = __ldg(&g_rowptr[v]);
    int end = __ldg(&g_rowptr[v + 1]);
    for (int e0 = beg; e0 < end; e0 += 32) {
        int cnt = end - e0;
        if (cnt > 32) cnt = 32;
        int s = (lane < cnt) ? __ldg(&g_srcidx[e0 + lane]) : 0;
        for (int j = 0; j < cnt; j++) {
            int sj = __shfl_sync(0xffffffffu, s, j);
            float4 gv = __ldg(&g4[(size_t)sj * 32 + lane]);
            acc.x += gv.x; acc.y += gv.y; acc.z += gv.z; acc.w += gv.w;
        }
    }

    float ds = __ldg(&g_dis[v]);
    float4 b = __ldg(((const float4*)bias) + lane);
    float4 o;
    o.x = fmaxf(fmaf(acc.x, ds, b.x), 0.f);
    o.y = fmaxf(fmaf(acc.y, ds, b.y), 0.f);
    o.z = fmaxf(fmaf(acc.z, ds, b.z), 0.f);
    o.w = fmaxf(fmaf(acc.w, ds, b.w), 0.f);
    ((float4*)out)[(size_t)v * 32 + lane] = o;
}

__global__ __launch_bounds__(256) void k_mlp2(
    const float* __restrict__ M, const float* __restrict__ W,
    const float* __restrict__ b, float* __restrict__ logits,
    float* __restrict__ probs, int n)
{
    __shared__ float Ws[DIM * 40];
    for (int i = threadIdx.x; i < DIM * 40; i += 256) Ws[i] = W[i];
    __syncthreads();

    int rl = threadIdx.x >> 3;
    int jg = threadIdx.x & 7;
    int row = blockIdx.x * 32 + rl;
    int rowc = (row < n) ? row : (n - 1);

    float acc[5] = {0.f, 0.f, 0.f, 0.f, 0.f};
    const float* mrow = M + (size_t)rowc * DIM;
    for (int k = 0; k < DIM; k += 4) {
        float4 a = __ldg((const float4*)(mrow + k));
        #pragma unroll
        for (int t = 0; t < 5; t++) {
            int j = jg * 5 + t;
            acc[t] += a.x * Ws[(k    ) * 40 + j];
            acc[t] += a.y * Ws[(k + 1) * 40 + j];
            acc[t] += a.z * Ws[(k + 2) * 40 + j];
            acc[t] += a.w * Ws[(k + 3) * 40 + j];
        }
    }
    #pragma unroll
    for (int t = 0; t < 5; t++) acc[t] += __ldg(&b[jg * 5 + t]);

    float mx = acc[0];
    #pragma unroll
    for (int t = 1; t < 5; t++) mx = fmaxf(mx, acc[t]);
    #pragma unroll
    for (int o = 1; o < 8; o <<= 1)
        mx = fmaxf(mx, __shfl_xor_sync(0xffffffffu, mx, o));
    float e[5], s = 0.f;
    #pragma unroll
    for (int t = 0; t < 5; t++) { e[t] = expf(acc[t] - mx); s += e[t]; }
    #pragma unroll
    for (int o = 1; o < 8; o <<= 1)
        s += __shfl_xor_sync(0xffffffffu, s, o);
    float inv = 1.f / s;

    if (row < n) {
        #pragma unroll
        for (int t = 0; t < 5; t++) {
            int j = jg * 5 + t;
            logits[(size_t)row * 40 + j] = acc[t];
            probs[(size_t)row * 40 + j]  = e[t] * inv;
        }
    }
}

extern "C" void kernel_launch(void* const* d_in, const int* in_sizes, int n_in,
                              void* d_out, int out_size)
{
    const float* x   = (const float*)d_in[0];
    const int*   ei  = (const int*)d_in[1];
    const float* W1  = (const float*)d_in[2];
    const float* b1  = (const float*)d_in[3];
    const float* W2  = (const float*)d_in[4];
    const float* b2  = (const float*)d_in[5];
    const float* W3  = (const float*)d_in[6];
    const float* b3  = (const float*)d_in[7];
    const float* Wm1 = (const float*)d_in[8];
    const float* bm1 = (const float*)d_in[9];
    const float* Wm2 = (const float*)d_in[10];
    const float* bm2 = (const float*)d_in[11];

    int n = in_sizes[0] / DIM;
    int E = in_sizes[1] / 2;
    const int* src = ei;
    const int* dst = ei + E;

    float* out    = (float*)d_out;
    float* logits = out;
    float* probs  = out + (size_t)n * 40;
    float* emb    = out + (size_t)n * 80;

    float *bufA, *bufB, *Wp;
    cudaGetSymbolAddress((void**)&bufA, g_bufA);
    cudaGetSymbolAddress((void**)&bufB, g_bufB);
    cudaGetSymbolAddress((void**)&Wp,   g_Wp);
    float* Wp1 = Wp;
    float* Wp2 = Wp + 64 * DIM * 2;
    float* Wp3 = Wp + 2 * 64 * DIM * 2;
    float* Wpm = Wp + 3 * 64 * DIM * 2;

    int gg = (n + 31) / 32;
    int ag = (n + 7) / 8;

    k_pre <<<(n + 255) / 256, 256>>>(W1, W2, W3, Wm1, n);
    k_hist<<<(E + 255) / 256, 256>>>(dst, E);
    k_scan<<<1, 1024>>>(n, E);
    // gemm1 kept in the profiled launch slot
    k_gemm<<<gg, 256>>>(x, Wp1, nullptr, bufA, n, 0);
    k_fill<<<(E + 255) / 256, 256>>>(src, dst, E);

    k_agg <<<ag, 256>>>(bufA, b1, bufB, n);
    k_gemm<<<gg, 256>>>(bufB, Wp2, nullptr, bufA, n, 0);
    k_agg <<<ag, 256>>>(bufA, b2, bufB, n);
    k_gemm<<<gg, 256>>>(bufB, Wp3, nullptr, bufA, n, 0);
    k_agg <<<ag, 256>>>(bufA, b3, emb, n);

    k_gemm<<<gg, 256>>>(emb,  Wpm, bm1, bufA, n, 1);
    k_mlp2<<<(n + 31) / 32, 256>>>(bufA, Wm2, bm2, logits, probs, n);
}